// round 1
// baseline (speedup 1.0000x reference)
#include <cuda_runtime.h>
#include <math.h>

#define Bc 4
#define Gc 2048
#define Dc 256
#define Hc 8
#define Lc 4
#define FFNc 1024
#define HDc 32
#define BGc (Bc*Gc)
#define NCc 32
#define Tc (Gc/NCc)   /* 64 */

// ---------------- scratch (no mallocs allowed) ----------------
__device__ float g_h[BGc*Dc];
__device__ float g_z[BGc*Dc];
__device__ float g_q[BGc*Dc];
__device__ float g_k[BGc*Dc];
__device__ float g_v[BGc*Dc];
__device__ float g_u[BGc*FFNc];
__device__ float g_cKV[Bc*Hc*NCc*HDc*HDc];
__device__ float g_cK[Bc*Hc*NCc*HDc];

// ---------------- embed: h = gene_emb + rotary-expression-embedding ----------------
__global__ void embed_kernel(const float* __restrict__ x, const float* __restrict__ ge){
    int row = blockIdx.x;          // b*G + g
    int d = threadIdx.x;           // 0..255
    int g = row % Gc;
    float xv = x[row];
    int i = (d < Dc/2) ? d : d - Dc/2;
    // inv_freq[i] = 100^{-(2i)/D} = exp(-(2i/D) * ln(100))
    float invf = expf(-((2.0f*(float)i)/(float)Dc) * 4.6051701859880914f);
    float f = xv * invf;
    float ree = (d < Dc/2) ? sinf(f) : cosf(f);
    if (xv == -10.0f) ree = 0.0f;
    g_h[(size_t)row*Dc + d] = ge[(size_t)g*Dc + d] + ree;
}

// ---------------- layernorm: warp-per-row ----------------
__global__ void ln_kernel(const float* __restrict__ in, const float* __restrict__ gamma,
                          const float* __restrict__ beta, float* __restrict__ out){
    int row  = blockIdx.x*8 + (threadIdx.x >> 5);
    int lane = threadIdx.x & 31;
    const float* p = in + (size_t)row*Dc;
    float vals[8]; float s = 0.f;
    #pragma unroll
    for (int j=0;j<8;j++){ vals[j] = p[lane + j*32]; s += vals[j]; }
    #pragma unroll
    for (int o=16;o;o>>=1) s += __shfl_xor_sync(0xffffffffu, s, o);
    float mu = s * (1.0f/(float)Dc);
    float vs = 0.f;
    #pragma unroll
    for (int j=0;j<8;j++){ float dd = vals[j]-mu; vs += dd*dd; }
    #pragma unroll
    for (int o=16;o;o>>=1) vs += __shfl_xor_sync(0xffffffffu, vs, o);
    float r = rsqrtf(vs*(1.0f/(float)Dc) + 1e-5f);
    float* po = out + (size_t)row*Dc;
    #pragma unroll
    for (int j=0;j<8;j++){
        int c = lane + j*32;
        po[c] = (vals[j]-mu)*r*gamma[c] + beta[c];
    }
}

// ---------------- SGEMM 128x128x8, 256 threads, 8x8 per thread ----------------
#define EPI_NONE   0
#define EPI_SQUARE 1
#define EPI_GELU   2

template<int EPI, bool RES>
__global__ void __launch_bounds__(256) sgemm_kernel(int M, int N, int K,
        const float* __restrict__ A, const float* __restrict__ Bw,
        const float* __restrict__ bias, float* __restrict__ C){
    __shared__ float As[8][128];
    __shared__ float Bs[8][128];
    int tid  = threadIdx.x;
    int col0 = blockIdx.x*128;
    int row0 = blockIdx.y*128;
    int tx = tid & 15, ty = tid >> 4;
    float acc[8][8];
    #pragma unroll
    for (int i=0;i<8;i++)
        #pragma unroll
        for (int j=0;j<8;j++) acc[i][j]=0.f;
    int arow  = tid >> 1;   // 0..127
    int ahalf = tid & 1;    // 0..1
    int bk  = tid >> 5;     // 0..7
    int bc4 = tid & 31;     // 0..31
    for (int k0 = 0; k0 < K; k0 += 8){
        float4 av = *(const float4*)(A + (size_t)(row0+arow)*K + k0 + ahalf*4);
        As[ahalf*4+0][arow] = av.x;
        As[ahalf*4+1][arow] = av.y;
        As[ahalf*4+2][arow] = av.z;
        As[ahalf*4+3][arow] = av.w;
        *(float4*)&Bs[bk][bc4*4] = *(const float4*)(Bw + (size_t)(k0+bk)*N + col0 + bc4*4);
        __syncthreads();
        #pragma unroll
        for (int kk=0;kk<8;kk++){
            float a[8], bb[8];
            *(float4*)&a[0]  = *(float4*)&As[kk][ty*8];
            *(float4*)&a[4]  = *(float4*)&As[kk][ty*8+4];
            *(float4*)&bb[0] = *(float4*)&Bs[kk][tx*8];
            *(float4*)&bb[4] = *(float4*)&Bs[kk][tx*8+4];
            #pragma unroll
            for (int i=0;i<8;i++)
                #pragma unroll
                for (int j=0;j<8;j++)
                    acc[i][j] += a[i]*bb[j];
        }
        __syncthreads();
    }
    #pragma unroll
    for (int i=0;i<8;i++){
        int m = row0 + ty*8 + i;
        #pragma unroll
        for (int j=0;j<8;j++){
            int n = col0 + tx*8 + j;
            float v = acc[i][j] + bias[n];
            if (EPI == EPI_SQUARE) v = v*v;
            if (EPI == EPI_GELU)   v = 0.5f*v*(1.0f + erff(v*0.70710678118654752f));
            if (RES) C[(size_t)m*N + n] += v;
            else     C[(size_t)m*N + n]  = v;
        }
    }
}

// ---------------- attention scan, chunked: A = per-chunk sums ----------------
// thread layout: tid = d*32 + m  (warp index = output dim d, lane = feature m)
__global__ void scanA_kernel(){
    int bid = blockIdx.x;            // bh*NC + c
    int c  = bid & (NCc-1);
    int bh = bid >> 5;               // NC = 32
    int b  = bh >> 3;                // H = 8
    int hh = bh & 7;
    int m = threadIdx.x & 31;
    int d = threadIdx.x >> 5;
    size_t base = ((size_t)(b*Gc + c*Tc))*Dc + hh*HDc;
    float S = 0.f, ks = 0.f;
    for (int s=0;s<Tc;s++){
        float km = g_k[base + (size_t)s*Dc + m];
        float vd = g_v[base + (size_t)s*Dc + d];
        S  += km*vd;
        ks += km;
    }
    g_cKV[(size_t)bid*1024 + threadIdx.x] = S;     // [bh][c][d][m]
    if (d == 0) g_cK[bid*32 + m] = ks;
}

// ---------------- B = exclusive prefix over chunks ----------------
__global__ void scanB_kernel(){
    int bh = blockIdx.x;
    int t  = threadIdx.x;
    float run = 0.f;
    for (int c=0;c<NCc;c++){
        size_t idx = ((size_t)(bh*NCc + c))*1024 + t;
        float val = g_cKV[idx];
        g_cKV[idx] = run;
        run += val;
    }
    if (t < 32){
        float run2 = 0.f;
        for (int c=0;c<NCc;c++){
            int idx = (bh*NCc + c)*32 + t;
            float val = g_cK[idx];
            g_cK[idx] = run2;
            run2 += val;
        }
    }
}

// ---------------- C = in-chunk inclusive scan + output (fused residual into h) --------
__global__ void scanC_kernel(){
    int bid = blockIdx.x;
    int c  = bid & (NCc-1);
    int bh = bid >> 5;
    int b  = bh >> 3;
    int hh = bh & 7;
    int m = threadIdx.x & 31;
    int d = threadIdx.x >> 5;
    size_t base = ((size_t)(b*Gc + c*Tc))*Dc + hh*HDc;
    float S  = g_cKV[(size_t)bid*1024 + threadIdx.x]; // S[m][d] held by lane m of warp d
    float ks = g_cK[bid*32 + m];                      // replicated per warp
    for (int s=0;s<Tc;s++){
        float qm = g_q[base + (size_t)s*Dc + m];
        float km = g_k[base + (size_t)s*Dc + m];
        float vd = g_v[base + (size_t)s*Dc + d];
        ks += km;
        S  += km*vd;
        float num = qm*S;
        float den = qm*ks;
        #pragma unroll
        for (int o=16;o;o>>=1){
            num += __shfl_xor_sync(0xffffffffu, num, o);
            den += __shfl_xor_sync(0xffffffffu, den, o);
        }
        if (m == 0) g_h[base + (size_t)s*Dc + d] += num/(den + 1e-16f);
    }
}

// ---------------- head: out = h @ Wo + bo ----------------
__global__ void out_kernel(const float* __restrict__ Wo, const float* __restrict__ bo,
                           float* __restrict__ out){
    int row  = blockIdx.x*8 + (threadIdx.x >> 5);
    int lane = threadIdx.x & 31;
    float s = 0.f;
    #pragma unroll
    for (int j=0;j<8;j++){
        int d = lane + j*32;
        s += g_h[(size_t)row*Dc + d] * Wo[d];
    }
    #pragma unroll
    for (int o=16;o;o>>=1) s += __shfl_xor_sync(0xffffffffu, s, o);
    if (lane == 0) out[row] = s + bo[0];
}

// ---------------- launch ----------------
extern "C" void kernel_launch(void* const* d_in, const int* in_sizes, int n_in,
                              void* d_out, int out_size){
    const float* x    = (const float*)d_in[0];
    const float* ge   = (const float*)d_in[1];
    const float* Wq   = (const float*)d_in[2];
    const float* bq   = (const float*)d_in[3];
    const float* Wk   = (const float*)d_in[4];
    const float* bk   = (const float*)d_in[5];
    const float* Wv   = (const float*)d_in[6];
    const float* bv   = (const float*)d_in[7];
    const float* ln1g = (const float*)d_in[8];
    const float* ln1b = (const float*)d_in[9];
    const float* ln2g = (const float*)d_in[10];
    const float* ln2b = (const float*)d_in[11];
    const float* WU   = (const float*)d_in[12];
    const float* bU   = (const float*)d_in[13];
    const float* WV   = (const float*)d_in[14];
    const float* bV   = (const float*)d_in[15];
    const float* Wo   = (const float*)d_in[16];
    const float* bo   = (const float*)d_in[17];
    float* out = (float*)d_out;

    float *ph, *pz, *pq, *pk, *pv, *pu;
    cudaGetSymbolAddress((void**)&ph, g_h);
    cudaGetSymbolAddress((void**)&pz, g_z);
    cudaGetSymbolAddress((void**)&pq, g_q);
    cudaGetSymbolAddress((void**)&pk, g_k);
    cudaGetSymbolAddress((void**)&pv, g_v);
    cudaGetSymbolAddress((void**)&pu, g_u);

    embed_kernel<<<BGc, Dc>>>(x, ge);

    for (int l=0;l<Lc;l++){
        // pre-LN attention block
        ln_kernel<<<BGc/8, 256>>>(ph, ln1g + l*Dc, ln1b + l*Dc, pz);
        dim3 gqkv(Dc/128, BGc/128);
        sgemm_kernel<EPI_SQUARE,false><<<gqkv,256>>>(BGc, Dc, Dc, pz, Wq + (size_t)l*Dc*Dc, bq + l*Dc, pq);
        sgemm_kernel<EPI_SQUARE,false><<<gqkv,256>>>(BGc, Dc, Dc, pz, Wk + (size_t)l*Dc*Dc, bk + l*Dc, pk);
        sgemm_kernel<EPI_NONE,  false><<<gqkv,256>>>(BGc, Dc, Dc, pz, Wv + (size_t)l*Dc*Dc, bv + l*Dc, pv);
        scanA_kernel<<<Bc*Hc*NCc, 1024>>>();
        scanB_kernel<<<Bc*Hc, 1024>>>();
        scanC_kernel<<<Bc*Hc*NCc, 1024>>>();

        // pre-LN FFN block
        ln_kernel<<<BGc/8, 256>>>(ph, ln2g + l*Dc, ln2b + l*Dc, pz);
        dim3 gu(FFNc/128, BGc/128);
        sgemm_kernel<EPI_GELU,false><<<gu,256>>>(BGc, FFNc, Dc, pz, WU + (size_t)l*Dc*FFNc, bU + l*FFNc, pu);
        dim3 gv(Dc/128, BGc/128);
        sgemm_kernel<EPI_NONE,true><<<gv,256>>>(BGc, Dc, FFNc, pu, WV + (size_t)l*FFNc*Dc, bV + l*Dc, ph);
    }

    out_kernel<<<BGc/8, 256>>>(Wo, bo, out);
}

// round 3
// speedup vs baseline: 1.6079x; 1.6079x over previous
#include <cuda_runtime.h>
#include <cuda_bf16.h>
#include <math.h>
#include <stdint.h>

#define Bc 4
#define Gc 2048
#define Dc 256
#define Hc 8
#define Lc 4
#define FFNc 1024
#define HDc 32
#define BGc (Bc*Gc)
#define NCc 32
#define Tc (Gc/NCc)   /* 64 */

// ---------------- scratch (no mallocs allowed) ----------------
__device__ float g_h[BGc*Dc];
__device__ float g_z[BGc*Dc];
__device__ float g_q[BGc*Dc];
__device__ float g_k[BGc*Dc];
__device__ float g_v[BGc*Dc];
__device__ float g_u[BGc*FFNc];
__device__ float g_cKV[Bc*Hc*NCc*HDc*HDc];
__device__ float g_cK[Bc*Hc*NCc*HDc];

// ---------------- embed ----------------
__global__ void embed_kernel(const float* __restrict__ x, const float* __restrict__ ge){
    int row = blockIdx.x;
    int d = threadIdx.x;
    int g = row % Gc;
    float xv = x[row];
    int i = (d < Dc/2) ? d : d - Dc/2;
    float invf = expf(-((2.0f*(float)i)/(float)Dc) * 4.6051701859880914f);
    float f = xv * invf;
    float ree = (d < Dc/2) ? sinf(f) : cosf(f);
    if (xv == -10.0f) ree = 0.0f;
    g_h[(size_t)row*Dc + d] = ge[(size_t)g*Dc + d] + ree;
}

// ---------------- layernorm: warp-per-row ----------------
__global__ void ln_kernel(const float* __restrict__ in, const float* __restrict__ gamma,
                          const float* __restrict__ beta, float* __restrict__ out){
    int row  = blockIdx.x*8 + (threadIdx.x >> 5);
    int lane = threadIdx.x & 31;
    const float* p = in + (size_t)row*Dc;
    float vals[8]; float s = 0.f;
    #pragma unroll
    for (int j=0;j<8;j++){ vals[j] = p[lane + j*32]; s += vals[j]; }
    #pragma unroll
    for (int o=16;o;o>>=1) s += __shfl_xor_sync(0xffffffffu, s, o);
    float mu = s * (1.0f/(float)Dc);
    float vs = 0.f;
    #pragma unroll
    for (int j=0;j<8;j++){ float dd = vals[j]-mu; vs += dd*dd; }
    #pragma unroll
    for (int o=16;o;o>>=1) vs += __shfl_xor_sync(0xffffffffu, vs, o);
    float r = rsqrtf(vs*(1.0f/(float)Dc) + 1e-5f);
    float* po = out + (size_t)row*Dc;
    #pragma unroll
    for (int j=0;j<8;j++){
        int c = lane + j*32;
        po[c] = (vals[j]-mu)*r*gamma[c] + beta[c];
    }
}

// ---------------- bf16 split-precision tensor-core GEMM ----------------
#define EPI_NONE   0
#define EPI_SQUARE 1
#define EPI_GELU   2

__device__ __forceinline__ uint16_t bfb(float x){
    __nv_bfloat16 h = __float2bfloat16(x);
    return *reinterpret_cast<uint16_t*>(&h);
}
__device__ __forceinline__ float bff(uint16_t b){
    __nv_bfloat16 h = *reinterpret_cast<__nv_bfloat16*>(&b);
    return __bfloat162float(h);
}
__device__ __forceinline__ uint32_t pack2(uint16_t lo, uint16_t hi){
    return ((uint32_t)hi<<16) | (uint32_t)lo;
}
__device__ __forceinline__ void mma16816(float* c, const uint32_t* a, const uint32_t* b){
    asm volatile("mma.sync.aligned.m16n8k16.row.col.f32.bf16.bf16.f32 "
        "{%0,%1,%2,%3}, {%4,%5,%6,%7}, {%8,%9}, {%0,%1,%2,%3};\n"
        : "+f"(c[0]),"+f"(c[1]),"+f"(c[2]),"+f"(c[3])
        : "r"(a[0]),"r"(a[1]),"r"(a[2]),"r"(a[3]), "r"(b[0]),"r"(b[1]));
}

// block tile 128x128, BK=32, 256 threads, warp tile 32x64 (warps 4x2)
#define ASTR 40      /* u16 stride for A smem (conflict-free) */
#define BSTR 136     /* u32 stride for B smem (conflict-free)  */

template<int EPI, bool RES>
__global__ void __launch_bounds__(256,1) mma_gemm(int M, int N, int K,
        const float* __restrict__ A, const float* __restrict__ Bw,
        const float* __restrict__ bias, float* __restrict__ C){
    __shared__ uint16_t Ah[128*ASTR];
    __shared__ uint16_t Al[128*ASTR];
    __shared__ uint32_t Bh[16*BSTR];
    __shared__ uint32_t Bl[16*BSTR];

    const int tid  = threadIdx.x;
    const int row0 = blockIdx.y*128;
    const int col0 = blockIdx.x*128;
    const int w    = tid>>5;
    const int wm   = w & 3;        // 0..3 (M)
    const int wn   = w >> 2;       // 0..1 (N)
    const int lane = tid & 31;
    const int g    = lane >> 2;
    const int t4   = lane & 3;

    float a_pre[16];
    float b_pre[16];

    // preload k-tile 0 into regs
    {
        #pragma unroll
        for (int i=0;i<4;i++){
            int id = tid + i*256;
            int r = id>>3, c = (id&7)*4;
            const float4 v = *(const float4*)(A + (size_t)(row0+r)*K + c);
            a_pre[i*4+0]=v.x; a_pre[i*4+1]=v.y; a_pre[i*4+2]=v.z; a_pre[i*4+3]=v.w;
        }
        #pragma unroll
        for (int i=0;i<8;i++){
            int id = tid + i*256;
            int k2 = id>>7, n = id&127;
            const float* p = Bw + (size_t)(2*k2)*N + col0 + n;
            b_pre[2*i+0] = p[0];
            b_pre[2*i+1] = p[N];
        }
    }

    float acc[2][8][4];
    #pragma unroll
    for (int mt=0;mt<2;mt++)
        #pragma unroll
        for (int nt=0;nt<8;nt++)
            #pragma unroll
            for (int q=0;q<4;q++) acc[mt][nt][q]=0.f;

    const int nk = K/32;
    for (int kt=0; kt<nk; kt++){
        // store prefetched regs -> smem with hi/lo bf16 split
        #pragma unroll
        for (int i=0;i<4;i++){
            int id = tid + i*256;
            int r = id>>3, c = (id&7)*4;
            uint16_t h[4], l[4];
            #pragma unroll
            for (int j=0;j<4;j++){
                float v = a_pre[i*4+j];
                h[j] = bfb(v);
                l[j] = bfb(v - bff(h[j]));
            }
            *(uint32_t*)&Ah[r*ASTR+c]   = pack2(h[0],h[1]);
            *(uint32_t*)&Ah[r*ASTR+c+2] = pack2(h[2],h[3]);
            *(uint32_t*)&Al[r*ASTR+c]   = pack2(l[0],l[1]);
            *(uint32_t*)&Al[r*ASTR+c+2] = pack2(l[2],l[3]);
        }
        #pragma unroll
        for (int i=0;i<8;i++){
            int id = tid + i*256;
            int k2 = id>>7, n = id&127;
            float v0 = b_pre[2*i+0], v1 = b_pre[2*i+1];
            uint16_t h0 = bfb(v0), h1 = bfb(v1);
            uint16_t l0 = bfb(v0 - bff(h0)), l1 = bfb(v1 - bff(h1));
            Bh[k2*BSTR+n] = pack2(h0,h1);
            Bl[k2*BSTR+n] = pack2(l0,l1);
        }
        __syncthreads();

        // prefetch next k-tile
        if (kt+1 < nk){
            int k0 = (kt+1)*32;
            #pragma unroll
            for (int i=0;i<4;i++){
                int id = tid + i*256;
                int r = id>>3, c = (id&7)*4;
                const float4 v = *(const float4*)(A + (size_t)(row0+r)*K + k0 + c);
                a_pre[i*4+0]=v.x; a_pre[i*4+1]=v.y; a_pre[i*4+2]=v.z; a_pre[i*4+3]=v.w;
            }
            #pragma unroll
            for (int i=0;i<8;i++){
                int id = tid + i*256;
                int k2 = id>>7, n = id&127;
                const float* p = Bw + (size_t)(k0+2*k2)*N + col0 + n;
                b_pre[2*i+0] = p[0];
                b_pre[2*i+1] = p[N];
            }
        }

        // compute 2 sub-steps of k16
        #pragma unroll
        for (int ks=0;ks<2;ks++){
            uint32_t afh[2][4], afl[2][4];
            #pragma unroll
            for (int mt=0;mt<2;mt++){
                int r  = wm*32 + mt*16 + g;
                int cb = ks*16 + t4*2;
                afh[mt][0]=*(const uint32_t*)&Ah[r*ASTR+cb];
                afh[mt][1]=*(const uint32_t*)&Ah[(r+8)*ASTR+cb];
                afh[mt][2]=*(const uint32_t*)&Ah[r*ASTR+cb+8];
                afh[mt][3]=*(const uint32_t*)&Ah[(r+8)*ASTR+cb+8];
                afl[mt][0]=*(const uint32_t*)&Al[r*ASTR+cb];
                afl[mt][1]=*(const uint32_t*)&Al[(r+8)*ASTR+cb];
                afl[mt][2]=*(const uint32_t*)&Al[r*ASTR+cb+8];
                afl[mt][3]=*(const uint32_t*)&Al[(r+8)*ASTR+cb+8];
            }
            #pragma unroll
            for (int nt=0;nt<8;nt++){
                int n  = wn*64 + nt*8 + g;
                int k2 = ks*8 + t4;
                uint32_t bhv[2], blv[2];
                bhv[0]=Bh[k2*BSTR+n]; bhv[1]=Bh[(k2+4)*BSTR+n];
                blv[0]=Bl[k2*BSTR+n]; blv[1]=Bl[(k2+4)*BSTR+n];
                #pragma unroll
                for (int mt=0;mt<2;mt++){
                    mma16816(acc[mt][nt], afh[mt], bhv);
                    mma16816(acc[mt][nt], afh[mt], blv);
                    mma16816(acc[mt][nt], afl[mt], bhv);
                }
            }
        }
        __syncthreads();
    }

    // epilogue
    #pragma unroll
    for (int mt=0;mt<2;mt++){
        #pragma unroll
        for (int nt=0;nt<8;nt++){
            int r = row0 + wm*32 + mt*16 + g;
            int n = col0 + wn*64 + nt*8 + t4*2;
            #pragma unroll
            for (int half=0; half<2; half++){
                int rr = r + half*8;
                float v0 = acc[mt][nt][half*2+0] + bias[n];
                float v1 = acc[mt][nt][half*2+1] + bias[n+1];
                if (EPI == EPI_SQUARE){ v0=v0*v0; v1=v1*v1; }
                if (EPI == EPI_GELU){
                    v0 = 0.5f*v0*(1.0f + erff(v0*0.70710678118654752f));
                    v1 = 0.5f*v1*(1.0f + erff(v1*0.70710678118654752f));
                }
                size_t idx = (size_t)rr*N + n;
                if (RES){ C[idx] += v0; C[idx+1] += v1; }
                else    { C[idx]  = v0; C[idx+1]  = v1; }
            }
        }
    }
}

// ---------------- attention scan, chunked ----------------
__global__ void scanA_kernel(){
    int bid = blockIdx.x;
    int c  = bid & (NCc-1);
    int bh = bid >> 5;
    int b  = bh >> 3;
    int hh = bh & 7;
    int m = threadIdx.x & 31;
    int d = threadIdx.x >> 5;
    size_t base = ((size_t)(b*Gc + c*Tc))*Dc + hh*HDc;
    float S = 0.f, ks = 0.f;
    for (int s=0;s<Tc;s++){
        float km = g_k[base + (size_t)s*Dc + m];
        float vd = g_v[base + (size_t)s*Dc + d];
        S  += km*vd;
        ks += km;
    }
    g_cKV[(size_t)bid*1024 + threadIdx.x] = S;
    if (d == 0) g_cK[bid*32 + m] = ks;
}

__global__ void scanB_kernel(){
    int bh = blockIdx.x;
    int t  = threadIdx.x;
    float run = 0.f;
    for (int c=0;c<NCc;c++){
        size_t idx = ((size_t)(bh*NCc + c))*1024 + t;
        float val = g_cKV[idx];
        g_cKV[idx] = run;
        run += val;
    }
    if (t < 32){
        float run2 = 0.f;
        for (int c=0;c<NCc;c++){
            int idx = (bh*NCc + c)*32 + t;
            float val = g_cK[idx];
            g_cK[idx] = run2;
            run2 += val;
        }
    }
}

__global__ void scanC_kernel(){
    int bid = blockIdx.x;
    int c  = bid & (NCc-1);
    int bh = bid >> 5;
    int b  = bh >> 3;
    int hh = bh & 7;
    int m = threadIdx.x & 31;
    int d = threadIdx.x >> 5;
    size_t base = ((size_t)(b*Gc + c*Tc))*Dc + hh*HDc;
    float S  = g_cKV[(size_t)bid*1024 + threadIdx.x];
    float ks = g_cK[bid*32 + m];
    for (int s=0;s<Tc;s++){
        float qm = g_q[base + (size_t)s*Dc + m];
        float km = g_k[base + (size_t)s*Dc + m];
        float vd = g_v[base + (size_t)s*Dc + d];
        ks += km;
        S  += km*vd;
        float num = qm*S;
        float den = qm*ks;
        #pragma unroll
        for (int o=16;o;o>>=1){
            num += __shfl_xor_sync(0xffffffffu, num, o);
            den += __shfl_xor_sync(0xffffffffu, den, o);
        }
        if (m == 0) g_h[base + (size_t)s*Dc + d] += num/(den + 1e-16f);
    }
}

// ---------------- head ----------------
__global__ void out_kernel(const float* __restrict__ Wo, const float* __restrict__ bo,
                           float* __restrict__ out){
    int row  = blockIdx.x*8 + (threadIdx.x >> 5);
    int lane = threadIdx.x & 31;
    float s = 0.f;
    #pragma unroll
    for (int j=0;j<8;j++){
        int d = lane + j*32;
        s += g_h[(size_t)row*Dc + d] * Wo[d];
    }
    #pragma unroll
    for (int o=16;o;o>>=1) s += __shfl_xor_sync(0xffffffffu, s, o);
    if (lane == 0) out[row] = s + bo[0];
}

// ---------------- launch ----------------
extern "C" void kernel_launch(void* const* d_in, const int* in_sizes, int n_in,
                              void* d_out, int out_size){
    const float* x    = (const float*)d_in[0];
    const float* ge   = (const float*)d_in[1];
    const float* Wq   = (const float*)d_in[2];
    const float* bq   = (const float*)d_in[3];
    const float* Wk   = (const float*)d_in[4];
    const float* bk   = (const float*)d_in[5];
    const float* Wv   = (const float*)d_in[6];
    const float* bv   = (const float*)d_in[7];
    const float* ln1g = (const float*)d_in[8];
    const float* ln1b = (const float*)d_in[9];
    const float* ln2g = (const float*)d_in[10];
    const float* ln2b = (const float*)d_in[11];
    const float* WU   = (const float*)d_in[12];
    const float* bU   = (const float*)d_in[13];
    const float* WV   = (const float*)d_in[14];
    const float* bV   = (const float*)d_in[15];
    const float* Wo   = (const float*)d_in[16];
    const float* bo   = (const float*)d_in[17];
    float* out = (float*)d_out;

    float *ph, *pz, *pq, *pk, *pv, *pu;
    cudaGetSymbolAddress((void**)&ph, g_h);
    cudaGetSymbolAddress((void**)&pz, g_z);
    cudaGetSymbolAddress((void**)&pq, g_q);
    cudaGetSymbolAddress((void**)&pk, g_k);
    cudaGetSymbolAddress((void**)&pv, g_v);
    cudaGetSymbolAddress((void**)&pu, g_u);

    embed_kernel<<<BGc, Dc>>>(x, ge);

    for (int l=0;l<Lc;l++){
        ln_kernel<<<BGc/8, 256>>>(ph, ln1g + l*Dc, ln1b + l*Dc, pz);
        dim3 gqkv(Dc/128, BGc/128);
        mma_gemm<EPI_SQUARE,false><<<gqkv,256>>>(BGc, Dc, Dc, pz, Wq + (size_t)l*Dc*Dc, bq + l*Dc, pq);
        mma_gemm<EPI_SQUARE,false><<<gqkv,256>>>(BGc, Dc, Dc, pz, Wk + (size_t)l*Dc*Dc, bk + l*Dc, pk);
        mma_gemm<EPI_NONE,  false><<<gqkv,256>>>(BGc, Dc, Dc, pz, Wv + (size_t)l*Dc*Dc, bv + l*Dc, pv);
        scanA_kernel<<<Bc*Hc*NCc, 1024>>>();
        scanB_kernel<<<Bc*Hc, 1024>>>();
        scanC_kernel<<<Bc*Hc*NCc, 1024>>>();

        ln_kernel<<<BGc/8, 256>>>(ph, ln2g + l*Dc, ln2b + l*Dc, pz);
        dim3 gu(FFNc/128, BGc/128);
        mma_gemm<EPI_GELU,false><<<gu,256>>>(BGc, FFNc, Dc, pz, WU + (size_t)l*Dc*FFNc, bU + l*FFNc, pu);
        dim3 gv(Dc/128, BGc/128);
        mma_gemm<EPI_NONE,true><<<gv,256>>>(BGc, Dc, FFNc, pu, WV + (size_t)l*FFNc*Dc, bV + l*Dc, ph);
    }

    out_kernel<<<BGc/8, 256>>>(Wo, bo, out);
}